// round 4
// baseline (speedup 1.0000x reference)
#include <cuda_runtime.h>
#include <cuda_fp16.h>
#include <cstdint>

#define ENC_DIM  512
#define PRED_DIM 640
#define JDIM     512
#define VOCAB    1024
#define NB       8
#define NT       256
#define NU       64
#define MTOT     (NB * NT * NU)          // 131072 output rows

// ---------------- scratch (device globals; no dynamic alloc) ----------------
__device__ float  g_enc_p [NB * NT * JDIM];            // 4 MB
__device__ float  g_pred_p[NB * NU * JDIM];            // 1 MB
__device__ __half g_W16   [JDIM * VOCAB];              // 1 MB, layout [k][n]
__device__ __half g_A     [(size_t)MTOT * JDIM];       // 128 MB, fp16 tanh(enc+pred), [m][k]

// ---------------- helpers ----------------
__device__ __forceinline__ uint32_t smem_u32(const void* p) {
    uint32_t a;
    asm("{ .reg .u64 t; cvta.to.shared.u64 t, %1; cvt.u32.u64 %0, t; }"
        : "=r"(a) : "l"(p));
    return a;
}

// tanh via EX2+RCP (2 MUFU), saturates correctly at +-inf
__device__ __forceinline__ float fast_tanh(float x) {
    float e = __expf(2.0f * x);
    return 1.0f - __fdividef(2.0f, e + 1.0f);
}

__device__ __forceinline__ void ldsm_x4(uint32_t* r, uint32_t addr) {
    asm volatile("ldmatrix.sync.aligned.m8n8.x4.shared.b16 {%0,%1,%2,%3}, [%4];"
                 : "=r"(r[0]), "=r"(r[1]), "=r"(r[2]), "=r"(r[3]) : "r"(addr));
}
__device__ __forceinline__ void ldsm_x4_t(uint32_t* r, uint32_t addr) {
    asm volatile("ldmatrix.sync.aligned.m8n8.x4.trans.shared.b16 {%0,%1,%2,%3}, [%4];"
                 : "=r"(r[0]), "=r"(r[1]), "=r"(r[2]), "=r"(r[3]) : "r"(addr));
}
__device__ __forceinline__ void mma_16816(float* d, const uint32_t* a, const uint32_t* b) {
    asm volatile(
        "mma.sync.aligned.m16n8k16.row.col.f32.f16.f16.f32 "
        "{%0,%1,%2,%3}, {%4,%5,%6,%7}, {%8,%9}, {%0,%1,%2,%3};"
        : "+f"(d[0]), "+f"(d[1]), "+f"(d[2]), "+f"(d[3])
        : "r"(a[0]), "r"(a[1]), "r"(a[2]), "r"(a[3]), "r"(b[0]), "r"(b[1]));
}

#define CP_ASYNC16(dst, src) \
    asm volatile("cp.async.cg.shared.global [%0], [%1], 16;" :: "r"(dst), "l"(src))
#define CP_COMMIT()  asm volatile("cp.async.commit_group;")
#define CP_WAIT1()   asm volatile("cp.async.wait_group 1;")

// ---------------- kernel 0: convert W_joint fp32 [k][n] -> fp16 [k][n] ----------------
__global__ void __launch_bounds__(256) wconv_kernel(const float* __restrict__ W) {
    int i = (blockIdx.x * 256 + threadIdx.x) * 4;
    float4 w = *(const float4*)(W + i);
    __half2 h0 = __floats2half2_rn(w.x, w.y);
    __half2 h1 = __floats2half2_rn(w.z, w.w);
    uint2 u;
    u.x = *reinterpret_cast<uint32_t*>(&h0);
    u.y = *reinterpret_cast<uint32_t*>(&h1);
    *(uint2*)(g_W16 + i) = u;
}

// ---------------- kernel 1: fp32 projection GEMM  C[M,J] = X[M,D]*W[D,J] + b ----------------
__global__ void __launch_bounds__(256) proj_kernel(const float* __restrict__ X,
                                                   const float* __restrict__ W,
                                                   const float* __restrict__ bias,
                                                   float* __restrict__ C,
                                                   int M, int D, int J) {
    __shared__ float Xs[16][68];
    __shared__ float Ws[16][68];
    int tid = threadIdx.x;
    int ty = tid >> 4, tx = tid & 15;
    int m0 = blockIdx.x * 64, j0 = blockIdx.y * 64;

    int lm  = tid >> 2,  lk4 = (tid & 3)  * 4;
    int ld  = tid >> 4,  lj4 = (tid & 15) * 4;

    float acc[4][4];
    #pragma unroll
    for (int i = 0; i < 4; i++)
        #pragma unroll
        for (int j = 0; j < 4; j++) acc[i][j] = 0.0f;

    for (int kc = 0; kc < D; kc += 16) {
        float4 xv = *(const float4*)&X[(size_t)(m0 + lm) * D + kc + lk4];
        Xs[lk4 + 0][lm] = xv.x;
        Xs[lk4 + 1][lm] = xv.y;
        Xs[lk4 + 2][lm] = xv.z;
        Xs[lk4 + 3][lm] = xv.w;
        *(float4*)&Ws[ld][lj4] = *(const float4*)&W[(size_t)(kc + ld) * J + j0 + lj4];
        __syncthreads();
        #pragma unroll
        for (int k = 0; k < 16; k++) {
            float4 av = *(const float4*)&Xs[k][ty * 4];
            float4 bv = *(const float4*)&Ws[k][tx * 4];
            float a_[4] = {av.x, av.y, av.z, av.w};
            float b_[4] = {bv.x, bv.y, bv.z, bv.w};
            #pragma unroll
            for (int i = 0; i < 4; i++)
                #pragma unroll
                for (int j = 0; j < 4; j++)
                    acc[i][j] = fmaf(a_[i], b_[j], acc[i][j]);
        }
        __syncthreads();
    }
    #pragma unroll
    for (int i = 0; i < 4; i++) {
        #pragma unroll
        for (int j = 0; j < 4; j++) {
            int jj = j0 + tx * 4 + j;
            C[(size_t)(m0 + ty * 4 + i) * J + jj] = acc[i][j] + bias[jj];
        }
    }
}

// ---------------- kernel 2: A = fp16 tanh(enc_p[bt] + pred_p[bu]), [m][k] ----------------
// block 256 threads -> 4 rows (512 elems each), 8 elems/thread
__global__ void __launch_bounds__(256) agen_kernel() {
    int r = blockIdx.x * 4 + (threadIdx.x >> 6);
    int c = (threadIdx.x & 63) * 8;
    // r = ((b*NT + t)*NU + u): enc row = r>>6, pred row = (r>>14)*NU + (r&63)
    const float* e = g_enc_p + (size_t)(r >> 6) * JDIM + c;
    const float* p = g_pred_p + ((size_t)(r >> 14) * NU + (r & 63)) * JDIM + c;
    float4 e0 = *(const float4*)e;
    float4 e1 = *(const float4*)(e + 4);
    float4 p0 = *(const float4*)p;
    float4 p1 = *(const float4*)(p + 4);
    float v0 = fast_tanh(e0.x + p0.x);
    float v1 = fast_tanh(e0.y + p0.y);
    float v2 = fast_tanh(e0.z + p0.z);
    float v3 = fast_tanh(e0.w + p0.w);
    float v4 = fast_tanh(e1.x + p1.x);
    float v5 = fast_tanh(e1.y + p1.y);
    float v6 = fast_tanh(e1.z + p1.z);
    float v7 = fast_tanh(e1.w + p1.w);
    __half2 q0 = __floats2half2_rn(v0, v1);
    __half2 q1 = __floats2half2_rn(v2, v3);
    __half2 q2 = __floats2half2_rn(v4, v5);
    __half2 q3 = __floats2half2_rn(v6, v7);
    uint4 q;
    q.x = *reinterpret_cast<uint32_t*>(&q0);
    q.y = *reinterpret_cast<uint32_t*>(&q1);
    q.z = *reinterpret_cast<uint32_t*>(&q2);
    q.w = *reinterpret_cast<uint32_t*>(&q3);
    *(uint4*)(g_A + (size_t)r * JDIM + c) = q;
}

// ---------------- kernel 3: mma.sync fp16 GEMM  out[M,1024] = A[M,512] * W16[512,1024] + b ----
// CTA tile 128(M) x 128(N) x K-chunks of 64; 8 warps (2M x 4N), warp tile 64x32.
// 3-stage cp.async pipeline. A smem [128][64] halves (128B rows, 8 chunks, xor swizzle).
// B smem [64][128] halves (256B rows, 16 chunks, xor swizzle).
#define STAGES     3
#define A_STG_SZ   16384
#define STG_STRIDE 32768
#define SMEM_MAIN  (STAGES * STG_STRIDE)   // 98304

__device__ __forceinline__ void load_stage(uint32_t sbase, int s, int kt, int tid,
                                           const __half* gA, const __half* gB) {
    uint32_t as = sbase + s * STG_STRIDE;
    uint32_t bs = as + A_STG_SZ;
    #pragma unroll
    for (int it = 0; it < 4; it++) {
        int idx = tid + it * 256;
        int r = idx >> 3, ck = idx & 7;               // A: 128 rows x 8 chunks
        const __half* src = gA + (size_t)r * JDIM + kt * 64 + ck * 8;
        uint32_t dst = as + r * 128 + ((ck ^ (r & 7)) * 16);
        CP_ASYNC16(dst, src);
    }
    #pragma unroll
    for (int it = 0; it < 4; it++) {
        int idx = tid + it * 256;
        int r = idx >> 4, cn = idx & 15;              // B: 64 rows x 16 chunks
        const __half* src = gB + (size_t)(kt * 64 + r) * VOCAB + cn * 8;
        uint32_t dst = bs + r * 256 + ((cn ^ (r & 7)) * 16);
        CP_ASYNC16(dst, src);
    }
}

__global__ void __launch_bounds__(256, 2)
joint_gemm(const float* __restrict__ b_joint, float* __restrict__ out) {
    extern __shared__ char smem[];
    uint32_t sbase = smem_u32(smem);
    const int tid  = threadIdx.x;
    const int wid  = tid >> 5, lane = tid & 31;
    const int wm   = wid >> 2, wn = wid & 3;          // 2 x 4 warp grid
    const int n0c  = blockIdx.x * 128;                // x fastest: A-tile L2 reuse
    const int gm0  = blockIdx.y * 128;

    const __half* gA = g_A + (size_t)gm0 * JDIM;
    const __half* gB = g_W16 + n0c;

    float acc[4][4][4];
    #pragma unroll
    for (int mt = 0; mt < 4; mt++)
        #pragma unroll
        for (int nt = 0; nt < 4; nt++)
            #pragma unroll
            for (int i = 0; i < 4; i++) acc[mt][nt][i] = 0.0f;

    load_stage(sbase, 0, 0, tid, gA, gB); CP_COMMIT();
    load_stage(sbase, 1, 1, tid, gA, gB); CP_COMMIT();

    const int lrow = lane & 15, lhi = lane >> 4;

    for (int kt = 0; kt < 8; kt++) {
        CP_WAIT1();
        __syncthreads();
        int pf = kt + 2;
        if (pf < 8) load_stage(sbase, pf % STAGES, pf, tid, gA, gB);
        CP_COMMIT();

        uint32_t as = sbase + (kt % STAGES) * STG_STRIDE;
        uint32_t bs = as + A_STG_SZ;
        #pragma unroll
        for (int kk = 0; kk < 4; kk++) {
            uint32_t af[4][4], bf[2][4];
            #pragma unroll
            for (int mt = 0; mt < 4; mt++) {
                int m  = wm * 64 + mt * 16 + lrow;
                int ch = (kk * 2 + lhi) ^ (m & 7);
                ldsm_x4(af[mt], as + m * 128 + ch * 16);
            }
            #pragma unroll
            for (int pr = 0; pr < 2; pr++) {
                int k  = kk * 16 + lrow;
                int ch = (wn * 4 + pr * 2 + lhi) ^ (k & 7);
                ldsm_x4_t(bf[pr], bs + k * 256 + ch * 16);
            }
            #pragma unroll
            for (int mt = 0; mt < 4; mt++)
                #pragma unroll
                for (int nt = 0; nt < 4; nt++)
                    mma_16816(acc[mt][nt], af[mt], &bf[nt >> 1][(nt & 1) * 2]);
        }
        __syncthreads();
    }

    // ---- epilogue: bias + streaming fp32 stores ----
    float2 bb[4];
    #pragma unroll
    for (int nt = 0; nt < 4; nt++) {
        int cc = n0c + wn * 32 + nt * 8 + (lane & 3) * 2;
        bb[nt] = *(const float2*)(b_joint + cc);
    }
    #pragma unroll
    for (int mt = 0; mt < 4; mt++) {
        int r0 = gm0 + wm * 64 + mt * 16 + (lane >> 2);
        #pragma unroll
        for (int nt = 0; nt < 4; nt++) {
            int cc = n0c + wn * 32 + nt * 8 + (lane & 3) * 2;
            float2 v0, v1;
            v0.x = acc[mt][nt][0] + bb[nt].x;
            v0.y = acc[mt][nt][1] + bb[nt].y;
            v1.x = acc[mt][nt][2] + bb[nt].x;
            v1.y = acc[mt][nt][3] + bb[nt].y;
            __stcs((float2*)(out + (size_t)r0 * VOCAB + cc), v0);
            __stcs((float2*)(out + (size_t)(r0 + 8) * VOCAB + cc), v1);
        }
    }
}

// ---------------- launch ----------------
extern "C" void kernel_launch(void* const* d_in, const int* in_sizes, int n_in,
                              void* d_out, int out_size) {
    const float* enc     = (const float*)d_in[0];
    const float* pred    = (const float*)d_in[1];
    const float* W_enc   = (const float*)d_in[2];
    const float* b_enc   = (const float*)d_in[3];
    const float* W_pred  = (const float*)d_in[4];
    const float* b_pred  = (const float*)d_in[5];
    const float* W_joint = (const float*)d_in[6];
    const float* b_joint = (const float*)d_in[7];
    float* out = (float*)d_out;
    (void)in_sizes; (void)n_in; (void)out_size;

    void* encp_v  = nullptr;
    void* predp_v = nullptr;
    cudaGetSymbolAddress(&encp_v,  g_enc_p);
    cudaGetSymbolAddress(&predp_v, g_pred_p);

    cudaFuncSetAttribute(joint_gemm, cudaFuncAttributeMaxDynamicSharedMemorySize,
                         SMEM_MAIN);

    // W_joint fp32 -> fp16 (same [k][n] layout)
    wconv_kernel<<<(JDIM * VOCAB) / (256 * 4), 256>>>(W_joint);
    // projections (fp32 exact)
    proj_kernel<<<dim3((NB * NT) / 64, JDIM / 64), 256>>>(
        enc, W_enc, b_enc, (float*)encp_v, NB * NT, ENC_DIM, JDIM);
    proj_kernel<<<dim3((NB * NU) / 64, JDIM / 64), 256>>>(
        pred, W_pred, b_pred, (float*)predp_v, NB * NU, PRED_DIM, JDIM);
    // A = fp16 tanh(enc_p (+) pred_p)
    agen_kernel<<<MTOT / 4, 256>>>();
    // big fp16 tensor-core GEMM + bias
    joint_gemm<<<dim3(VOCAB / 128, MTOT / 128), 256, SMEM_MAIN>>>(b_joint, out);
}

// round 5
// speedup vs baseline: 1.1150x; 1.1150x over previous
#include <cuda_runtime.h>
#include <cuda_fp16.h>
#include <cstdint>

#define ENC_DIM  512
#define PRED_DIM 640
#define JDIM     512
#define VOCAB    1024
#define NB       8
#define NT       256
#define NU       64
#define MTOT     (NB * NT * NU)          // 131072 output rows

// ---------------- scratch (device globals; no dynamic alloc) ----------------
__device__ float  g_enc_p [NB * NT * JDIM];            // 4 MB
__device__ float  g_pred_p[NB * NU * JDIM];            // 1 MB
__device__ __half g_W16   [JDIM * VOCAB];              // 1 MB, [k][n]
__device__ __half g_A     [(size_t)MTOT * JDIM];       // 128 MB fp16 tanh(enc+pred), [m][k]
// fp16 copies for tensor-core projections
__device__ __half g_enc16 [NB * NT * ENC_DIM];
__device__ __half g_pred16[NB * NU * PRED_DIM];
__device__ __half g_Wenc16 [ENC_DIM * JDIM];
__device__ __half g_Wpred16[PRED_DIM * JDIM];

// ---------------- helpers ----------------
__device__ __forceinline__ uint32_t smem_u32(const void* p) {
    uint32_t a;
    asm("{ .reg .u64 t; cvta.to.shared.u64 t, %1; cvt.u32.u64 %0, t; }"
        : "=r"(a) : "l"(p));
    return a;
}

// tanh via EX2+RCP (2 MUFU), saturates correctly at +-inf
__device__ __forceinline__ float fast_tanh(float x) {
    float e = __expf(2.0f * x);
    return 1.0f - __fdividef(2.0f, e + 1.0f);
}

__device__ __forceinline__ void ldsm_x4(uint32_t* r, uint32_t addr) {
    asm volatile("ldmatrix.sync.aligned.m8n8.x4.shared.b16 {%0,%1,%2,%3}, [%4];"
                 : "=r"(r[0]), "=r"(r[1]), "=r"(r[2]), "=r"(r[3]) : "r"(addr));
}
__device__ __forceinline__ void ldsm_x4_t(uint32_t* r, uint32_t addr) {
    asm volatile("ldmatrix.sync.aligned.m8n8.x4.trans.shared.b16 {%0,%1,%2,%3}, [%4];"
                 : "=r"(r[0]), "=r"(r[1]), "=r"(r[2]), "=r"(r[3]) : "r"(addr));
}
__device__ __forceinline__ void mma_16816(float* d, const uint32_t* a, const uint32_t* b) {
    asm volatile(
        "mma.sync.aligned.m16n8k16.row.col.f32.f16.f16.f32 "
        "{%0,%1,%2,%3}, {%4,%5,%6,%7}, {%8,%9}, {%0,%1,%2,%3};"
        : "+f"(d[0]), "+f"(d[1]), "+f"(d[2]), "+f"(d[3])
        : "r"(a[0]), "r"(a[1]), "r"(a[2]), "r"(a[3]), "r"(b[0]), "r"(b[1]));
}

#define CP_ASYNC16(dst, src) \
    asm volatile("cp.async.cg.shared.global [%0], [%1], 16;" :: "r"(dst), "l"(src))
#define CP_COMMIT()  asm volatile("cp.async.commit_group;")
#define CP_WAIT1()   asm volatile("cp.async.wait_group 1;")

// ---------------- generic fp32 -> fp16 conversion (4 elems/thread) ----------------
__global__ void __launch_bounds__(256) f2h_kernel(const float* __restrict__ src,
                                                  __half* __restrict__ dst) {
    int i = (blockIdx.x * 256 + threadIdx.x) * 4;
    float4 w = *(const float4*)(src + i);
    __half2 h0 = __floats2half2_rn(w.x, w.y);
    __half2 h1 = __floats2half2_rn(w.z, w.w);
    uint2 u;
    u.x = *reinterpret_cast<uint32_t*>(&h0);
    u.y = *reinterpret_cast<uint32_t*>(&h1);
    *(uint2*)(dst + i) = u;
}

// ---------------- shared GEMM plumbing: 128x128 CTA tile, 8 warps (2x4), 3-stage ----
#define STAGES     3
#define A_STG_SZ   16384
#define STG_STRIDE 32768
#define SMEM_MAIN  (STAGES * STG_STRIDE)   // 98304

// A: 128 rows x 64 k fp16 (128B rows, 8 chunks, xor swizzle)
// B: 64 k x 128 n fp16 (256B rows, 16 chunks, xor swizzle); ldN = row stride of B/global C
__device__ __forceinline__ void load_stage_g(uint32_t sbase, int s, int kt, int tid,
                                             const __half* gA, int ldA,
                                             const __half* gB, int ldN) {
    uint32_t as = sbase + s * STG_STRIDE;
    uint32_t bs = as + A_STG_SZ;
    #pragma unroll
    for (int it = 0; it < 4; it++) {
        int idx = tid + it * 256;
        int r = idx >> 3, ck = idx & 7;
        const __half* src = gA + (size_t)r * ldA + kt * 64 + ck * 8;
        uint32_t dst = as + r * 128 + ((ck ^ (r & 7)) * 16);
        CP_ASYNC16(dst, src);
    }
    #pragma unroll
    for (int it = 0; it < 4; it++) {
        int idx = tid + it * 256;
        int r = idx >> 4, cn = idx & 15;
        const __half* src = gB + (size_t)(kt * 64 + r) * ldN + cn * 8;
        uint32_t dst = bs + r * 256 + ((cn ^ (r & 7)) * 16);
        CP_ASYNC16(dst, src);
    }
}

struct Frag { float acc[4][4][4]; };

__device__ __forceinline__ void gemm_mainloop(uint32_t sbase, int tid, int nKt,
                                              const __half* gA, int ldA,
                                              const __half* gB, int ldN,
                                              Frag& f) {
    const int wid = tid >> 5, lane = tid & 31;
    const int wm = wid >> 2, wn = wid & 3;
    const int lrow = lane & 15, lhi = lane >> 4;

    load_stage_g(sbase, 0, 0, tid, gA, ldA, gB, ldN); CP_COMMIT();
    load_stage_g(sbase, 1, 1, tid, gA, ldA, gB, ldN); CP_COMMIT();

    for (int kt = 0; kt < nKt; kt++) {
        CP_WAIT1();
        __syncthreads();
        int pf = kt + 2;
        if (pf < nKt) load_stage_g(sbase, pf % STAGES, pf, tid, gA, ldA, gB, ldN);
        CP_COMMIT();

        uint32_t as = sbase + (kt % STAGES) * STG_STRIDE;
        uint32_t bs = as + A_STG_SZ;
        #pragma unroll
        for (int kk = 0; kk < 4; kk++) {
            uint32_t af[4][4], bf[2][4];
            #pragma unroll
            for (int mt = 0; mt < 4; mt++) {
                int m  = wm * 64 + mt * 16 + lrow;
                int ch = (kk * 2 + lhi) ^ (m & 7);
                ldsm_x4(af[mt], as + m * 128 + ch * 16);
            }
            #pragma unroll
            for (int pr = 0; pr < 2; pr++) {
                int k  = kk * 16 + lrow;
                int ch = (wn * 4 + pr * 2 + lhi) ^ (k & 7);
                ldsm_x4_t(bf[pr], bs + k * 256 + ch * 16);
            }
            #pragma unroll
            for (int mt = 0; mt < 4; mt++)
                #pragma unroll
                for (int nt = 0; nt < 4; nt++)
                    mma_16816(f.acc[mt][nt], af[mt], &bf[nt >> 1][(nt & 1) * 2]);
        }
        __syncthreads();
    }
}

// ---------------- projection GEMM (fp16 TC): C[M,J] = X[M,D]*W[D,J] + bias ----------------
__global__ void __launch_bounds__(256, 2)
proj_mma(const __half* __restrict__ X, const __half* __restrict__ W,
         const float* __restrict__ bias, float* __restrict__ C, int D, int J) {
    extern __shared__ char smem[];
    uint32_t sbase = smem_u32(smem);
    const int tid = threadIdx.x;
    const int wid = tid >> 5, lane = tid & 31;
    const int wm = wid >> 2, wn = wid & 3;
    const int n0c = blockIdx.x * 128;
    const int gm0 = blockIdx.y * 128;

    Frag f;
    #pragma unroll
    for (int mt = 0; mt < 4; mt++)
        #pragma unroll
        for (int nt = 0; nt < 4; nt++)
            #pragma unroll
            for (int i = 0; i < 4; i++) f.acc[mt][nt][i] = 0.0f;

    gemm_mainloop(sbase, tid, D / 64, X + (size_t)gm0 * D, D, W + n0c, J, f);

    float2 bb[4];
    #pragma unroll
    for (int nt = 0; nt < 4; nt++) {
        int cc = n0c + wn * 32 + nt * 8 + (lane & 3) * 2;
        bb[nt] = *(const float2*)(bias + cc);
    }
    #pragma unroll
    for (int mt = 0; mt < 4; mt++) {
        int r0 = gm0 + wm * 64 + mt * 16 + (lane >> 2);
        #pragma unroll
        for (int nt = 0; nt < 4; nt++) {
            int cc = n0c + wn * 32 + nt * 8 + (lane & 3) * 2;
            float2 v0, v1;
            v0.x = f.acc[mt][nt][0] + bb[nt].x;
            v0.y = f.acc[mt][nt][1] + bb[nt].y;
            v1.x = f.acc[mt][nt][2] + bb[nt].x;
            v1.y = f.acc[mt][nt][3] + bb[nt].y;
            *(float2*)(C + (size_t)r0 * J + cc) = v0;
            *(float2*)(C + (size_t)(r0 + 8) * J + cc) = v1;
        }
    }
}

// ---------------- A = fp16 tanh(enc_p[bt] + pred_p[bu]), [m][k] ----------------
__global__ void __launch_bounds__(256) agen_kernel() {
    int r = blockIdx.x * 4 + (threadIdx.x >> 6);
    int c = (threadIdx.x & 63) * 8;
    const float* e = g_enc_p + (size_t)(r >> 6) * JDIM + c;
    const float* p = g_pred_p + ((size_t)(r >> 14) * NU + (r & 63)) * JDIM + c;
    float4 e0 = *(const float4*)e;
    float4 e1 = *(const float4*)(e + 4);
    float4 p0 = *(const float4*)p;
    float4 p1 = *(const float4*)(p + 4);
    float v0 = fast_tanh(e0.x + p0.x);
    float v1 = fast_tanh(e0.y + p0.y);
    float v2 = fast_tanh(e0.z + p0.z);
    float v3 = fast_tanh(e0.w + p0.w);
    float v4 = fast_tanh(e1.x + p1.x);
    float v5 = fast_tanh(e1.y + p1.y);
    float v6 = fast_tanh(e1.z + p1.z);
    float v7 = fast_tanh(e1.w + p1.w);
    __half2 q0 = __floats2half2_rn(v0, v1);
    __half2 q1 = __floats2half2_rn(v2, v3);
    __half2 q2 = __floats2half2_rn(v4, v5);
    __half2 q3 = __floats2half2_rn(v6, v7);
    uint4 q;
    q.x = *reinterpret_cast<uint32_t*>(&q0);
    q.y = *reinterpret_cast<uint32_t*>(&q1);
    q.z = *reinterpret_cast<uint32_t*>(&q2);
    q.w = *reinterpret_cast<uint32_t*>(&q3);
    *(uint4*)(g_A + (size_t)r * JDIM + c) = q;
}

// ---------------- main GEMM: out[M,1024] = A[M,512]*W16[512,1024] + b_joint ----------------
__global__ void __launch_bounds__(256, 2)
joint_gemm(const float* __restrict__ b_joint, float* __restrict__ out) {
    extern __shared__ char smem[];
    uint32_t sbase = smem_u32(smem);
    const int tid = threadIdx.x;
    const int wid = tid >> 5, lane = tid & 31;
    const int wm = wid >> 2, wn = wid & 3;
    const int n0c = blockIdx.x * 128;              // x fastest: A-tile L2 reuse
    const int gm0 = blockIdx.y * 128;

    Frag f;
    #pragma unroll
    for (int mt = 0; mt < 4; mt++)
        #pragma unroll
        for (int nt = 0; nt < 4; nt++)
            #pragma unroll
            for (int i = 0; i < 4; i++) f.acc[mt][nt][i] = 0.0f;

    gemm_mainloop(sbase, tid, JDIM / 64, g_A + (size_t)gm0 * JDIM, JDIM,
                  g_W16 + n0c, VOCAB, f);

    float2 bb[4];
    #pragma unroll
    for (int nt = 0; nt < 4; nt++) {
        int cc = n0c + wn * 32 + nt * 8 + (lane & 3) * 2;
        bb[nt] = *(const float2*)(b_joint + cc);
    }
    #pragma unroll
    for (int mt = 0; mt < 4; mt++) {
        int r0 = gm0 + wm * 64 + mt * 16 + (lane >> 2);
        #pragma unroll
        for (int nt = 0; nt < 4; nt++) {
            int cc = n0c + wn * 32 + nt * 8 + (lane & 3) * 2;
            float2 v0, v1;
            v0.x = f.acc[mt][nt][0] + bb[nt].x;
            v0.y = f.acc[mt][nt][1] + bb[nt].y;
            v1.x = f.acc[mt][nt][2] + bb[nt].x;
            v1.y = f.acc[mt][nt][3] + bb[nt].y;
            __stcs((float2*)(out + (size_t)r0 * VOCAB + cc), v0);
            __stcs((float2*)(out + (size_t)(r0 + 8) * VOCAB + cc), v1);
        }
    }
}

// ---------------- launch ----------------
extern "C" void kernel_launch(void* const* d_in, const int* in_sizes, int n_in,
                              void* d_out, int out_size) {
    const float* enc     = (const float*)d_in[0];
    const float* pred    = (const float*)d_in[1];
    const float* W_enc   = (const float*)d_in[2];
    const float* b_enc   = (const float*)d_in[3];
    const float* W_pred  = (const float*)d_in[4];
    const float* b_pred  = (const float*)d_in[5];
    const float* W_joint = (const float*)d_in[6];
    const float* b_joint = (const float*)d_in[7];
    float* out = (float*)d_out;
    (void)in_sizes; (void)n_in; (void)out_size;

    void *encp_v, *predp_v, *w16_v, *enc16_v, *pred16_v, *wenc16_v, *wpred16_v;
    cudaGetSymbolAddress(&encp_v,   g_enc_p);
    cudaGetSymbolAddress(&predp_v,  g_pred_p);
    cudaGetSymbolAddress(&w16_v,    g_W16);
    cudaGetSymbolAddress(&enc16_v,  g_enc16);
    cudaGetSymbolAddress(&pred16_v, g_pred16);
    cudaGetSymbolAddress(&wenc16_v, g_Wenc16);
    cudaGetSymbolAddress(&wpred16_v, g_Wpred16);

    cudaFuncSetAttribute(joint_gemm, cudaFuncAttributeMaxDynamicSharedMemorySize, SMEM_MAIN);
    cudaFuncSetAttribute(proj_mma,   cudaFuncAttributeMaxDynamicSharedMemorySize, SMEM_MAIN);

    // fp32 -> fp16 conversions
    f2h_kernel<<<(JDIM * VOCAB)      / 1024, 256>>>(W_joint, (__half*)w16_v);
    f2h_kernel<<<(NB*NT*ENC_DIM)     / 1024, 256>>>(enc,    (__half*)enc16_v);
    f2h_kernel<<<(NB*NU*PRED_DIM)    / 1024, 256>>>(pred,   (__half*)pred16_v);
    f2h_kernel<<<(ENC_DIM * JDIM)    / 1024, 256>>>(W_enc,  (__half*)wenc16_v);
    f2h_kernel<<<(PRED_DIM * JDIM)   / 1024, 256>>>(W_pred, (__half*)wpred16_v);

    // tensor-core projections (fp32 accum + bias)
    proj_mma<<<dim3(JDIM / 128, (NB * NT) / 128), 256, SMEM_MAIN>>>(
        (const __half*)enc16_v, (const __half*)wenc16_v, b_enc, (float*)encp_v,
        ENC_DIM, JDIM);
    proj_mma<<<dim3(JDIM / 128, (NB * NU) / 128), 256, SMEM_MAIN>>>(
        (const __half*)pred16_v, (const __half*)wpred16_v, b_pred, (float*)predp_v,
        PRED_DIM, JDIM);

    // A = fp16 tanh(enc_p (+) pred_p)
    agen_kernel<<<MTOT / 4, 256>>>();
    // big fp16 tensor-core GEMM + bias
    joint_gemm<<<dim3(VOCAB / 128, MTOT / 128), 256, SMEM_MAIN>>>(b_joint, out);
}